// round 14
// baseline (speedup 1.0000x reference)
#include <cuda_runtime.h>
#include <cuda_fp16.h>
#include <stdint.h>
#include <math.h>

#define GMAX 100000

// ---------------- static scratch ----------------
__device__ float  g_segsum[(size_t)GMAX*256];
__device__ float  g_segcnt[GMAX];
__device__ __half g_W1h[18*4096];   // fragment-packed fp16, K padded to 288 (18 k16-blocks)
__device__ __half g_W2h[16*4096];
__device__ __half g_Wc1h[16*4096];

// ---------------- node smem (bytes) ----------------
// [0,65536)        W slots 2 x 32KB (K=64 chunks)
// [65536,131072)   H1h blocked: 16 blks x (128 rows x 16 fp16) = 64KB
// [131072,163840)  X bufs 2 x 16KB
// Y fp32 overlay [0,133120) pitch 260 — epilogue-2 only
#define NOFF_H1   65536
#define NOFF_X    131072
#define NOFF_B1   163840
#define NOFF_B2   164864
#define NOFF_SEG  165888
#define NOFF_MB   166400
#define SMB_N     166464

// ---------------- head smem ----------------
#define HOFF_X    32768
#define HOFF_W2S  135168
#define HOFF_B1   145408
#define HOFF_B2   146432
#define HOFF_INV  146496
#define HOFF_MB   147008
#define SMB_H     147456

__device__ __forceinline__ float gelu(float x){
    return 0.5f * x * (1.0f + erff(x * 0.70710678118654752f));
}
__device__ __forceinline__ void mma16(float* c, const unsigned* a, unsigned b0, unsigned b1){
    asm volatile(
        "mma.sync.aligned.m16n8k16.row.col.f32.f16.f16.f32 "
        "{%0,%1,%2,%3},{%4,%5,%6,%7},{%8,%9},{%0,%1,%2,%3};\n"
        : "+f"(c[0]), "+f"(c[1]), "+f"(c[2]), "+f"(c[3])
        : "r"(a[0]), "r"(a[1]), "r"(a[2]), "r"(a[3]), "r"(b0), "r"(b1));
}
__device__ __forceinline__ void bulkcp(uint32_t dst, const void* src, uint32_t bytes, uint32_t mbar){
    asm volatile("cp.async.bulk.shared::cluster.global.mbarrier::complete_tx::bytes [%0], [%1], %2, [%3];"
        :: "r"(dst), "l"(src), "r"(bytes), "r"(mbar) : "memory");
}
__device__ __forceinline__ uint32_t s2u(const void* p){
    uint32_t a; asm("{ .reg .u64 t; cvta.to.shared.u64 t, %1; cvt.u32.u64 %0, t; }" : "=r"(a) : "l"(p));
    return a;
}
#define MB_INIT(a,c)  asm volatile("mbarrier.init.shared.b64 [%0], %1;" :: "r"(a), "r"(c) : "memory")
#define MB_EXPECT(a,b) asm volatile("mbarrier.arrive.expect_tx.shared.b64 _, [%0], %1;" :: "r"(a), "r"(b) : "memory")
#define FEN_ASYNC()   asm volatile("fence.proxy.async.shared::cta;" ::: "memory")
#define MB_WAIT(a,p) do{ uint32_t _m=(a); uint32_t _p=(p); uint32_t _d; \
    asm volatile("{\n\t.reg .pred p;\n\tmbarrier.try_wait.parity.acquire.cta.shared::cta.b64 p, [%1], %2;\n\tselp.b32 %0,1,0,p;\n\t}" \
        : "=r"(_d) : "r"(_m), "r"(_p) : "memory"); \
    if(!_d){ asm volatile("{\n\t.reg .pred P1;\nWL_%=:\n\tmbarrier.try_wait.parity.acquire.cta.shared::cta.b64 P1, [%0], %1, 0x989680;\n\t@P1 bra.uni WD_%=;\n\tbra.uni WL_%=;\nWD_%=:\n\t}" \
        :: "r"(_m), "r"(_p) : "memory"); } }while(0)

// ---------------------------------------------------------------------------
// prep: zero segsum, counts, fragment-pack weights (fp16)
// ---------------------------------------------------------------------------
__device__ __forceinline__ void packWh(__half* dst, const float* src, int Ktrue, int nk16,
                                       size_t t0, size_t stride)
{
    size_t tot = (size_t)nk16 * 4096;
    for (size_t i = t0; i < tot; i += stride){
        int half = (int)(i & 1), reg = (int)((i >> 1) & 1), s = (int)((i >> 2) & 1);
        int T = (int)((i >> 3) & 31), p = (int)((i >> 8) & 15), kk = (int)(i >> 12);
        int n = (2*p + s)*8 + (T >> 2);
        int k = kk*16 + (T & 3)*2 + reg*8 + half;
        dst[i] = __float2half_rn((k < Ktrue) ? src[(size_t)k*256 + n] : 0.f);
    }
}

__global__ void prep_kernel(const float* __restrict__ W1, const float* __restrict__ W2,
                            const float* __restrict__ Wc1,
                            const int* __restrict__ seg, int N, int G)
{
    size_t stride = (size_t)gridDim.x * blockDim.x;
    size_t t0 = (size_t)blockIdx.x * blockDim.x + threadIdx.x;
    float4* z = (float4*)g_segsum;
    for (size_t i = t0; i < (size_t)G*64; i += stride) z[i] = make_float4(0.f,0.f,0.f,0.f);
    for (size_t g = t0; g < (size_t)G; g += stride){
        int gi = (int)g;
        int lo = 0, hi = N;
        while (lo < hi){ int m = (lo+hi) >> 1; if (seg[m] < gi) lo = m+1; else hi = m; }
        int lb = lo; hi = N;
        while (lo < hi){ int m = (lo+hi) >> 1; if (seg[m] <= gi) lo = m+1; else hi = m; }
        g_segcnt[g] = (float)(lo - lb);
    }
    packWh(g_W1h,  W1,  272, 18, t0, stride);
    packWh(g_W2h,  W2,  256, 16, t0, stride);
    packWh(g_Wc1h, Wc1, 256, 16, t0, stride);
}

// ---------------------------------------------------------------------------
// one k16 step; A blocked [blk][128][16] fp16 pair-perm; NP n16-col fragments
// ---------------------------------------------------------------------------
template<int NP>
__device__ __forceinline__ void kstep16b(const __half* Ab, int blk, const __half* Wb, int step,
                                         int pbase, int row0, int lane, float c[4][NP*2][4])
{
    const __half* Abase = Ab + (size_t)blk*2048;
    unsigned a[4][4];
    #pragma unroll
    for (int mm = 0; mm < 4; mm++){
        int r = row0 + mm*16 + (lane >> 2);
        uint2 lo = *(const uint2*)(Abase + r*16 + (lane & 3)*4);
        uint2 hi = *(const uint2*)(Abase + (r + 8)*16 + (lane & 3)*4);
        a[mm][0] = lo.x; a[mm][1] = hi.x; a[mm][2] = lo.y; a[mm][3] = hi.y;
    }
    uint4 b[NP];
    #pragma unroll
    for (int p = 0; p < NP; p++)
        b[p] = *(const uint4*)(Wb + step*4096 + (((pbase + p)*32 + lane)*8));
    #pragma unroll
    for (int mm = 0; mm < 4; mm++){
        #pragma unroll
        for (int p = 0; p < NP; p++){
            mma16(c[mm][p*2],     a[mm], b[p].x, b[p].y);
            mma16(c[mm][p*2 + 1], a[mm], b[p].z, b[p].w);
        }
    }
}

// pair-perm 16 fp32 -> 16 fp16: (0,1),(8,9),(2,3),(10,11),(4,5),(12,13),(6,7),(14,15)
__device__ __forceinline__ void stage_blk16(const float* v, __half* dst)
{
    __half2 h[8];
    #pragma unroll
    for (int q = 0; q < 4; q++){
        h[q*2]     = __floats2half2_rn(v[2*q],     v[2*q + 1]);
        h[q*2 + 1] = __floats2half2_rn(v[2*q + 8], v[2*q + 9]);
    }
    uint32_t* d = (uint32_t*)dst;
    asm volatile("st.shared.v4.b32 [%0], {%1,%2,%3,%4};" :: "l"(d),
        "r"(*(uint32_t*)&h[0]), "r"(*(uint32_t*)&h[1]), "r"(*(uint32_t*)&h[2]), "r"(*(uint32_t*)&h[3]) : "memory");
    asm volatile("st.shared.v4.b32 [%0], {%1,%2,%3,%4};" :: "l"(d + 4),
        "r"(*(uint32_t*)&h[4]), "r"(*(uint32_t*)&h[5]), "r"(*(uint32_t*)&h[6]), "r"(*(uint32_t*)&h[7]) : "memory");
}

// ---------------------------------------------------------------------------
// node kernel: 512 thr, 16 warps (2 row x 8 col groups), warp tile 64x32
// 9 rounds: 0..4 layer-1 (K=64,64,64,64,32), 5..8 layer-2 (K=64)
// ---------------------------------------------------------------------------
__device__ __forceinline__ void node_ldx16(float* kv, const float* hf, const float* sf,
                                           int r0, int N, int rc, int tid)
{
    int r = tid & 127, t4 = tid >> 7;             // t4 in 0..3: one 16-col block
    int gr = r0 + r, kg = rc*64 + t4*16;
    float4 v[4];
    #pragma unroll
    for (int q = 0; q < 4; q++) v[q] = make_float4(0.f,0.f,0.f,0.f);
    if (gr < N){
        if (kg < 256){
            const float4* p = (const float4*)(hf + (size_t)gr*256 + kg);
            #pragma unroll
            for (int q = 0; q < 4; q++) v[q] = p[q];
        } else if (kg < 272){
            const float4* p = (const float4*)(sf + (size_t)gr*16);
            #pragma unroll
            for (int q = 0; q < 4; q++) v[q] = p[q];
        }
    }
    #pragma unroll
    for (int q = 0; q < 4; q++){
        kv[q*4+0]=v[q].x; kv[q*4+1]=v[q].y; kv[q*4+2]=v[q].z; kv[q*4+3]=v[q].w;
    }
}
__device__ __forceinline__ void stage16(const float* kv, __half* xb, int tid)
{
    int r = tid & 127, t4 = tid >> 7;
    stage_blk16(kv, xb + ((size_t)t4*128 + r)*16);
}

__global__ void __launch_bounds__(512, 1)
node_kernel(const float* __restrict__ hf, const float* __restrict__ sf,
            const float* __restrict__ b1, const float* __restrict__ b2,
            const int* __restrict__ seg, int N)
{
    extern __shared__ float smraw[];
    char* sb = (char*)smraw;
    uint32_t B0 = s2u(sb);
    __half* H1h = (__half*)(sb + NOFF_H1);
    float*  Ysm = (float*)sb;
    float*  b1s = (float*)(sb + NOFF_B1);
    float*  b2s = (float*)(sb + NOFF_B2);
    int*   segs = (int*)(sb + NOFF_SEG);
    const uint32_t MB = B0 + NOFF_MB;

    int tid = threadIdx.x, lane = tid & 31, warp = tid >> 5;
    int row0 = (warp & 1) * 64, cg = warp >> 1;     // cg 0..7
    int col0 = cg * 32;
    int r0 = blockIdx.x * 128;

    if (tid < 256){ b1s[tid] = b1[tid]; b2s[tid] = b2[tid]; }
    if (tid >= 256 && tid < 384){ int r = r0 + tid - 256; segs[tid - 256] = (r < N) ? seg[r] : -1; }
    if (tid == 0){
        MB_INIT(MB, 1); MB_INIT(MB + 8, 1);
        FEN_ASYNC();
        MB_EXPECT(MB, 32768u);
        bulkcp(B0, g_W1h, 32768, MB);
    }
    __syncthreads();

    float kv[16];
    node_ldx16(kv, hf, sf, r0, N, 0, tid);

    float c[4][4][4];
    #pragma unroll
    for (int mm = 0; mm < 4; mm++)
        #pragma unroll
        for (int nn = 0; nn < 4; nn++)
            #pragma unroll
            for (int q = 0; q < 4; q++) c[mm][nn][q] = 0.f;

    for (int rc = 0; rc < 9; rc++){
        int b = rc & 1;
        bool L1 = (rc < 5);
        if (L1){
            stage16(kv, (__half*)(sb + NOFF_X + b*16384), tid);
            if (rc < 4) node_ldx16(kv, hf, sf, r0, N, rc + 1, tid);
        }
        __syncthreads();
        if (tid == 0 && rc < 8){
            int nc = rc + 1, nb = nc & 1;
            uint32_t bytes = (nc == 4) ? 16384u : 32768u;
            const __half* src = (nc < 5) ? (g_W1h + nc*16384) : (g_W2h + (nc - 5)*16384);
            MB_EXPECT(MB + nb*8, bytes);
            bulkcp(B0 + nb*32768, src, bytes, MB + nb*8);
        }
        MB_WAIT(MB + b*8, (rc >> 1) & 1);
        const __half* Wb = (const __half*)(sb + b*32768);
        if (L1){
            const __half* Ab = (const __half*)(sb + NOFF_X + b*16384);
            kstep16b<2>(Ab, 0, Wb, 0, cg*2, row0, lane, c);
            kstep16b<2>(Ab, 1, Wb, 1, cg*2, row0, lane, c);
            if (rc != 4){
                kstep16b<2>(Ab, 2, Wb, 2, cg*2, row0, lane, c);
                kstep16b<2>(Ab, 3, Wb, 3, cg*2, row0, lane, c);
            }
        } else {
            int kb = (rc - 5)*4;
            kstep16b<2>(H1h, kb + 0, Wb, 0, cg*2, row0, lane, c);
            kstep16b<2>(H1h, kb + 1, Wb, 1, cg*2, row0, lane, c);
            kstep16b<2>(H1h, kb + 2, Wb, 2, cg*2, row0, lane, c);
            kstep16b<2>(H1h, kb + 3, Wb, 3, cg*2, row0, lane, c);
        }

        if (rc == 4){
            __syncthreads();
            // epilogue-1: H1h = fp16(gelu(c + b1)), blocked pair-perm layout
            #pragma unroll
            for (int mm = 0; mm < 4; mm++){
                #pragma unroll
                for (int nn = 0; nn < 4; nn++){
                    int rr = row0 + mm*16 + (lane >> 2);
                    int cc = col0 + nn*8 + 2*(lane & 3);
                    int blk = cc >> 4;
                    int pos = ((cc & 7) >> 1)*4 + ((cc >> 3) & 1)*2;
                    __half* p0 = H1h + ((size_t)blk*128 + rr)*16 + pos;
                    float bb0 = b1s[cc], bb1 = b1s[cc + 1];
                    *(__half2*)p0         = __floats2half2_rn(gelu(c[mm][nn][0] + bb0), gelu(c[mm][nn][1] + bb1));
                    *(__half2*)(p0 + 128) = __floats2half2_rn(gelu(c[mm][nn][2] + bb0), gelu(c[mm][nn][3] + bb1));
                    #pragma unroll
                    for (int q = 0; q < 4; q++) c[mm][nn][q] = 0.f;
                }
            }
        }
    }
    __syncthreads();

    // epilogue-2: Y = c + b2 (fp32, pitch 260, overlays W slots + H1 — reads done)
    #pragma unroll
    for (int mm = 0; mm < 4; mm++){
        #pragma unroll
        for (int nn = 0; nn < 4; nn++){
            int rr = row0 + mm*16 + (lane >> 2);
            int cc = col0 + nn*8 + 2*(lane & 3);
            float bb0 = b2s[cc], bb1 = b2s[cc + 1];
            *(float2*)(Ysm + rr*260 + cc)       = make_float2(c[mm][nn][0] + bb0, c[mm][nn][1] + bb1);
            *(float2*)(Ysm + (rr + 8)*260 + cc) = make_float2(c[mm][nn][2] + bb0, c[mm][nn][3] + bb1);
        }
    }
    __syncthreads();

    // sorted-run segment accumulate: 512 thr = 256 cols x 2 row-halves
    {
        int col = tid & 255, half = tid >> 8;
        int rbeg = half*64, rend = rbeg + 64;
        float acc = 0.f; int cur = -1;
        for (int r = rbeg; r < rend; r++){
            int s = segs[r];
            if (s != cur){
                if (cur >= 0) atomicAdd(&g_segsum[(size_t)cur*256 + col], acc);
                acc = 0.f; cur = s;
            }
            if (s >= 0) acc += Ysm[r*260 + col];
        }
        if (cur >= 0) atomicAdd(&g_segsum[(size_t)cur*256 + col], acc);
    }
}

// ---------------------------------------------------------------------------
// head kernel: 256 thr, 8 warps (2 row x 4 col groups), warp tile 64x64
// ---------------------------------------------------------------------------
__device__ __forceinline__ void head_ldx32(float* kv, const float* invc, int g0, int G, int rc, int tid)
{
    int r = tid & 127, t2 = tid >> 7;
    int g = g0 + r, kg = rc*32 + t2*16;
    float4 v[4];
    #pragma unroll
    for (int q = 0; q < 4; q++) v[q] = make_float4(0.f,0.f,0.f,0.f);
    if (g < G){
        const float4* p = (const float4*)(g_segsum + (size_t)g*256 + kg);
        float iv = invc[r];
        #pragma unroll
        for (int q = 0; q < 4; q++){
            float4 t = p[q];
            v[q] = make_float4(t.x*iv, t.y*iv, t.z*iv, t.w*iv);
        }
    }
    #pragma unroll
    for (int q = 0; q < 4; q++){
        kv[q*4+0]=v[q].x; kv[q*4+1]=v[q].y; kv[q*4+2]=v[q].z; kv[q*4+3]=v[q].w;
    }
}

__global__ void __launch_bounds__(256, 1)
head_kernel(const float* __restrict__ bc1, const float* __restrict__ Wc2,
            const float* __restrict__ bc2, float* __restrict__ out, int G)
{
    extern __shared__ float smraw[];
    char* sb = (char*)smraw;
    uint32_t B0 = s2u(sb);
    float* Hs   = (float*)sb;
    float* w2s  = (float*)(sb + HOFF_W2S);
    float* bc1s = (float*)(sb + HOFF_B1);
    float* bc2s = (float*)(sb + HOFF_B2);
    float* invc = (float*)(sb + HOFF_INV);
    const uint32_t MB = B0 + HOFF_MB;

    int tid = threadIdx.x, lane = tid & 31, warp = tid >> 5;
    int row0 = (warp & 1) * 64, cg = warp >> 1;
    int col0 = cg * 64;
    int g0 = blockIdx.x * 128;

    bc1s[tid] = bc1[tid];
    for (int i = tid; i < 2560; i += 256) w2s[i] = Wc2[i];
    if (tid < 16) bc2s[tid] = (tid < 10) ? bc2[tid] : 0.f;
    if (tid < 128){
        int g = g0 + tid;
        float cc = (g < G) ? g_segcnt[g] : 1.f;
        invc[tid] = 1.f / fmaxf(cc, 1.f);
    }
    if (tid == 0){
        MB_INIT(MB, 1); MB_INIT(MB + 8, 1);
        FEN_ASYNC();
        MB_EXPECT(MB, 16384u);
        bulkcp(B0, g_Wc1h, 16384, MB);
    }
    __syncthreads();

    float kv[16];
    head_ldx32(kv, invc, g0, G, 0, tid);

    float c[4][8][4];
    #pragma unroll
    for (int mm = 0; mm < 4; mm++)
        #pragma unroll
        for (int nn = 0; nn < 8; nn++)
            #pragma unroll
            for (int q = 0; q < 4; q++) c[mm][nn][q] = 0.f;

    for (int rc = 0; rc < 8; rc++){
        int b = rc & 1;
        {
            int r = tid & 127, t2 = tid >> 7;
            stage_blk16(kv, (__half*)(sb + HOFF_X + b*8192) + ((size_t)t2*128 + r)*16);
        }
        if (rc < 7) head_ldx32(kv, invc, g0, G, rc + 1, tid);
        __syncthreads();
        if (tid == 0 && rc < 7){
            int nc = rc + 1, nb = nc & 1;
            MB_EXPECT(MB + nb*8, 16384u);
            bulkcp(B0 + nb*16384, g_Wc1h + nc*8192, 16384, MB + nb*8);
        }
        MB_WAIT(MB + b*8, (rc >> 1) & 1);
        const __half* Wb = (const __half*)(sb + b*16384);
        const __half* Ab = (const __half*)(sb + HOFF_X + b*8192);
        kstep16b<4>(Ab, 0, Wb, 0, cg*4, row0, lane, c);
        kstep16b<4>(Ab, 1, Wb, 1, cg*4, row0, lane, c);
    }
    __syncthreads();

    // epilogue: Hs = gelu(c + bc1), fp32, pitch 264
    #pragma unroll
    for (int mm = 0; mm < 4; mm++){
        #pragma unroll
        for (int nn = 0; nn < 8; nn++){
            int rr = row0 + mm*16 + (lane >> 2);
            int cc = col0 + nn*8 + 2*(lane & 3);
            float bb0 = bc1s[cc], bb1 = bc1s[cc + 1];
            *(float2*)(Hs + rr*264 + cc)       = make_float2(gelu(c[mm][nn][0] + bb0), gelu(c[mm][nn][1] + bb1));
            *(float2*)(Hs + (rr + 8)*264 + cc) = make_float2(gelu(c[mm][nn][2] + bb0), gelu(c[mm][nn][3] + bb1));
        }
    }
    __syncthreads();

    // final: out[128,10] = Hs[128,256] @ Wc2 + bc2 (FFMA)
    for (int i = tid; i < 1280; i += 256){
        int r = i / 10, cl = i - r*10;
        float acc = bc2s[cl];
        const float* hp = Hs + r*264;
        #pragma unroll 8
        for (int k = 0; k < 256; k++) acc += hp[k] * w2s[k*10 + cl];
        int g = g0 + r;
        if (g < G) out[(size_t)g*10 + cl] = acc;
    }
}

// ---------------------------------------------------------------------------
extern "C" void kernel_launch(void* const* d_in, const int* in_sizes, int n_in,
                              void* d_out, int out_size)
{
    const float* hf  = (const float*)d_in[0];
    const float* sf  = (const float*)d_in[1];
    const float* W1  = (const float*)d_in[2];
    const float* b1  = (const float*)d_in[3];
    const float* W2  = (const float*)d_in[4];
    const float* b2  = (const float*)d_in[5];
    const float* Wc1 = (const float*)d_in[6];
    const float* bc1 = (const float*)d_in[7];
    const float* Wc2 = (const float*)d_in[8];
    const float* bc2 = (const float*)d_in[9];
    const int*   seg = (const int*)d_in[10];

    int N = in_sizes[0] / 256;
    int G = out_size / 10;

    cudaFuncSetAttribute(node_kernel, cudaFuncAttributeMaxDynamicSharedMemorySize, SMB_N);
    cudaFuncSetAttribute(head_kernel, cudaFuncAttributeMaxDynamicSharedMemorySize, SMB_H);

    prep_kernel<<<2048, 256>>>(W1, W2, Wc1, seg, N, G);
    node_kernel<<<(N + 127) / 128, 512, SMB_N>>>(hf, sf, b1, b2, seg, N);
    head_kernel<<<(G + 127) / 128, 256, SMB_H>>>(bc1, Wc2, bc2, (float*)d_out, G);
}